// round 3
// baseline (speedup 1.0000x reference)
#include <cuda_runtime.h>
#include <cuda_bf16.h>
#include <cstdint>

#define N_NODES 20000
#define N_EDGES 320000
#define IN_FEATS 512
#define HIDDEN 64
#define HEADS 8
#define D0 512           // HEADS*HIDDEN
#define OUT_DIM 64
#define NEG_SLOPE 0.2f
#define MAXDEG 512

// ---------------- scratch (device globals; no allocation allowed) ----------------
__device__ float g_feat0[(size_t)N_NODES * D0];     // layer0 projected feats [N, 8*64]
__device__ float g_h1[(size_t)N_NODES * D0];        // elu(aggregated layer0)  [N, 512]
__device__ float g_feat1[(size_t)N_NODES * OUT_DIM];// layer1 projected feats [N, 64]
__device__ float g_el0[N_NODES * HEADS];
__device__ float g_er0[N_NODES * HEADS];
__device__ float g_el1[N_NODES];
__device__ float g_er1[N_NODES];
__device__ int   g_counts[N_NODES];
__device__ int   g_rowoff[N_NODES + 1];
__device__ int   g_cursor[N_NODES];
__device__ int   g_csrsrc[N_EDGES];

__device__ __forceinline__ float lrelu(float x) { return x > 0.f ? x : NEG_SLOPE * x; }
#define NEG_INF __int_as_float(0xff800000)

// ---------------- CSR build ----------------
__global__ void zero_counts_kernel() {
    int i = blockIdx.x * blockDim.x + threadIdx.x;
    if (i < N_NODES) g_counts[i] = 0;
}

__global__ void count_kernel(const int* __restrict__ dst) {
    int e = blockIdx.x * blockDim.x + threadIdx.x;
    if (e < N_EDGES) atomicAdd(&g_counts[dst[e]], 1);
}

__global__ void scan_kernel() {
    __shared__ int s[1024];
    const int tid = threadIdx.x;
    const int CH = (N_NODES + 1023) / 1024;   // 20
    int b = tid * CH;
    int e = min(b + CH, N_NODES);
    int local = 0;
    for (int i = b; i < e; i++) local += g_counts[i];
    s[tid] = local;
    __syncthreads();
    for (int off = 1; off < 1024; off <<= 1) {
        int add = (tid >= off) ? s[tid - off] : 0;
        __syncthreads();
        s[tid] += add;
        __syncthreads();
    }
    int run = s[tid] - local;                 // exclusive prefix
    for (int i = b; i < e; i++) {
        g_rowoff[i] = run;
        g_cursor[i] = run;
        run += g_counts[i];
    }
    if (tid == 1023) g_rowoff[N_NODES] = s[1023];
}

__global__ void scatter_kernel(const int* __restrict__ src, const int* __restrict__ dst) {
    int e = blockIdx.x * blockDim.x + threadIdx.x;
    if (e < N_EDGES) {
        int pos = atomicAdd(&g_cursor[dst[e]], 1);
        g_csrsrc[pos] = src[e];
    }
}

// ---------------- fp32 SGEMM: C[M,N] = A[M,K] * B[K,N] ----------------
// BM=128, BN=64, BK=16, 256 threads, 8x4 per thread.
#define GBM 128
#define GBN 64
#define GBK 16
__global__ void __launch_bounds__(256) sgemm_kernel(
    const float* __restrict__ A, const float* __restrict__ B, float* __restrict__ C,
    int M, int N, int K)
{
    __shared__ float As[GBK][GBM];
    __shared__ float Bs[GBK][GBN];
    const int bm = blockIdx.y * GBM;
    const int bn = blockIdx.x * GBN;
    const int tid = threadIdx.x;
    const int tx = tid & 15, ty = tid >> 4;
    float acc[8][4];
#pragma unroll
    for (int i = 0; i < 8; i++)
#pragma unroll
        for (int j = 0; j < 4; j++) acc[i][j] = 0.f;

    const int arow = tid >> 2;          // 0..63
    const int acol = (tid & 3) << 2;    // 0,4,8,12
    const int brow = tid >> 4;          // 0..15
    const int bcol = (tid & 15) << 2;   // 0..60

    for (int k0 = 0; k0 < K; k0 += GBK) {
#pragma unroll
        for (int r = 0; r < 2; r++) {
            int m = arow + (r << 6);
            float4 v = make_float4(0.f, 0.f, 0.f, 0.f);
            if (bm + m < M) v = *(const float4*)(A + (size_t)(bm + m) * K + (k0 + acol));
            As[acol + 0][m] = v.x;
            As[acol + 1][m] = v.y;
            As[acol + 2][m] = v.z;
            As[acol + 3][m] = v.w;
        }
        *(float4*)&Bs[brow][bcol] = *(const float4*)(B + (size_t)(k0 + brow) * N + (bn + bcol));
        __syncthreads();
#pragma unroll
        for (int k = 0; k < GBK; k++) {
            float a[8], b[4];
#pragma unroll
            for (int i = 0; i < 8; i++) a[i] = As[k][ty * 8 + i];
#pragma unroll
            for (int j = 0; j < 4; j++) b[j] = Bs[k][tx * 4 + j];
#pragma unroll
            for (int i = 0; i < 8; i++)
#pragma unroll
                for (int j = 0; j < 4; j++)
                    acc[i][j] = fmaf(a[i], b[j], acc[i][j]);
        }
        __syncthreads();
    }
#pragma unroll
    for (int i = 0; i < 8; i++) {
        int m = bm + ty * 8 + i;
        if (m < M)
            *(float4*)(C + (size_t)m * N + bn + tx * 4) =
                make_float4(acc[i][0], acc[i][1], acc[i][2], acc[i][3]);
    }
}

// ---------------- el/er for layer 0: warp per (node, head) ----------------
__global__ void __launch_bounds__(256) eler0_kernel(const float* __restrict__ al,
                                                    const float* __restrict__ ar)
{
    const int n = blockIdx.x;               // one node per block
    const int h = threadIdx.x >> 5;         // 8 warps = 8 heads
    const int lane = threadIdx.x & 31;
    const float* f = g_feat0 + (size_t)n * D0 + h * HIDDEN;
    float2 fv = *(const float2*)(f + lane * 2);
    float2 alv = *(const float2*)(al + h * HIDDEN + lane * 2);
    float2 arv = *(const float2*)(ar + h * HIDDEN + lane * 2);
    float sl = fv.x * alv.x + fv.y * alv.y;
    float sr = fv.x * arv.x + fv.y * arv.y;
#pragma unroll
    for (int o = 16; o; o >>= 1) {
        sl += __shfl_xor_sync(0xffffffffu, sl, o);
        sr += __shfl_xor_sync(0xffffffffu, sr, o);
    }
    if (lane == 0) {
        g_el0[n * HEADS + h] = sl;
        g_er0[n * HEADS + h] = sr;
    }
}

// ---------------- el/er for layer 1: warp per node ----------------
__global__ void __launch_bounds__(256) eler1_kernel(const float* __restrict__ al,
                                                    const float* __restrict__ ar)
{
    const int gw = blockIdx.x * 8 + (threadIdx.x >> 5);
    const int lane = threadIdx.x & 31;
    if (gw >= N_NODES) return;
    const float* f = g_feat1 + (size_t)gw * OUT_DIM;
    float2 fv = *(const float2*)(f + lane * 2);
    float2 alv = *(const float2*)(al + lane * 2);
    float2 arv = *(const float2*)(ar + lane * 2);
    float sl = fv.x * alv.x + fv.y * alv.y;
    float sr = fv.x * arv.x + fv.y * arv.y;
#pragma unroll
    for (int o = 16; o; o >>= 1) {
        sl += __shfl_xor_sync(0xffffffffu, sl, o);
        sr += __shfl_xor_sync(0xffffffffu, sr, o);
    }
    if (lane == 0) {
        g_el1[gw] = sl;
        g_er1[gw] = sr;
    }
}

// ---------------- layer-0 softmax + aggregation + ELU: block per dst node ----------------
__global__ void __launch_bounds__(256) gat_agg0_kernel()
{
    const int n = blockIdx.x;
    const int beg = g_rowoff[n];
    const int deg = g_rowoff[n + 1] - beg;
    const int tid = threadIdx.x;

    if (deg == 0) {   // elu(0) = 0
        g_h1[(size_t)n * D0 + tid] = 0.f;
        g_h1[(size_t)n * D0 + tid + 256] = 0.f;
        return;
    }

    __shared__ float s_alpha[HEADS][MAXDEG];
    __shared__ int   s_src[MAXDEG];
    __shared__ float s_m[HEADS], s_rinv[HEADS];

    const int h = tid >> 5;
    const int lane = tid & 31;
    const float ern = g_er0[n * HEADS + h];

    const int c0 = tid, c1 = tid + 256;
    const int h0 = c0 >> 6, h1i = c1 >> 6;

    if (deg <= MAXDEG) {
        for (int j = tid; j < deg; j += 256) s_src[j] = g_csrsrc[beg + j];
        __syncthreads();

        float m = NEG_INF;
        for (int j = lane; j < deg; j += 32) {
            float e = lrelu(g_el0[s_src[j] * HEADS + h] + ern);
            s_alpha[h][j] = e;
            m = fmaxf(m, e);
        }
#pragma unroll
        for (int o = 16; o; o >>= 1) m = fmaxf(m, __shfl_xor_sync(0xffffffffu, m, o));
        float sum = 0.f;
        for (int j = lane; j < deg; j += 32) {
            float ex = __expf(s_alpha[h][j] - m);
            s_alpha[h][j] = ex;
            sum += ex;
        }
#pragma unroll
        for (int o = 16; o; o >>= 1) sum += __shfl_xor_sync(0xffffffffu, sum, o);
        float rinv = 1.f / fmaxf(sum, 1e-9f);
        for (int j = lane; j < deg; j += 32) s_alpha[h][j] *= rinv;
        __syncthreads();

        float acc0 = 0.f, acc1 = 0.f;
#pragma unroll 4
        for (int j = 0; j < deg; j++) {
            const float* fr = g_feat0 + (size_t)s_src[j] * D0;
            acc0 = fmaf(s_alpha[h0][j], fr[c0], acc0);
            acc1 = fmaf(s_alpha[h1i][j], fr[c1], acc1);
        }
        g_h1[(size_t)n * D0 + c0] = acc0 > 0.f ? acc0 : __expf(acc0) - 1.f;
        g_h1[(size_t)n * D0 + c1] = acc1 > 0.f ? acc1 : __expf(acc1) - 1.f;
    } else {
        // huge-degree fallback: recompute e, no SMEM caches
        float m = NEG_INF;
        for (int j = lane; j < deg; j += 32)
            m = fmaxf(m, lrelu(g_el0[g_csrsrc[beg + j] * HEADS + h] + ern));
#pragma unroll
        for (int o = 16; o; o >>= 1) m = fmaxf(m, __shfl_xor_sync(0xffffffffu, m, o));
        float sum = 0.f;
        for (int j = lane; j < deg; j += 32)
            sum += __expf(lrelu(g_el0[g_csrsrc[beg + j] * HEADS + h] + ern) - m);
#pragma unroll
        for (int o = 16; o; o >>= 1) sum += __shfl_xor_sync(0xffffffffu, sum, o);
        if (lane == 0) { s_m[h] = m; s_rinv[h] = 1.f / fmaxf(sum, 1e-9f); }
        __syncthreads();

        const float m0 = s_m[h0], r0 = s_rinv[h0];
        const float m1 = s_m[h1i], r1 = s_rinv[h1i];
        const float e0n = g_er0[n * HEADS + h0], e1n = g_er0[n * HEADS + h1i];
        float acc0 = 0.f, acc1 = 0.f;
        for (int j = 0; j < deg; j++) {
            int s = g_csrsrc[beg + j];
            float a0 = __expf(lrelu(g_el0[s * HEADS + h0] + e0n) - m0) * r0;
            float a1 = __expf(lrelu(g_el0[s * HEADS + h1i] + e1n) - m1) * r1;
            const float* fr = g_feat0 + (size_t)s * D0;
            acc0 = fmaf(a0, fr[c0], acc0);
            acc1 = fmaf(a1, fr[c1], acc1);
        }
        g_h1[(size_t)n * D0 + c0] = acc0 > 0.f ? acc0 : __expf(acc0) - 1.f;
        g_h1[(size_t)n * D0 + c1] = acc1 > 0.f ? acc1 : __expf(acc1) - 1.f;
    }
}

// ---------------- layer-1 softmax + aggregation (1 head, 64 dims): block per dst node ----------------
__global__ void __launch_bounds__(64) gat_agg1_kernel(float* __restrict__ out)
{
    const int n = blockIdx.x;
    const int beg = g_rowoff[n];
    const int deg = g_rowoff[n + 1] - beg;
    const int tid = threadIdx.x;

    if (deg == 0) { out[(size_t)n * OUT_DIM + tid] = 0.f; return; }

    __shared__ float s_alpha[MAXDEG];
    __shared__ int   s_src[MAXDEG];
    __shared__ float s_mr[2];

    const float ern = g_er1[n];

    if (deg <= MAXDEG) {
        for (int j = tid; j < deg; j += 64) s_src[j] = g_csrsrc[beg + j];
        __syncthreads();
        if (tid < 32) {
            float m = NEG_INF;
            for (int j = tid; j < deg; j += 32) {
                float e = lrelu(g_el1[s_src[j]] + ern);
                s_alpha[j] = e;
                m = fmaxf(m, e);
            }
#pragma unroll
            for (int o = 16; o; o >>= 1) m = fmaxf(m, __shfl_xor_sync(0xffffffffu, m, o));
            float sum = 0.f;
            for (int j = tid; j < deg; j += 32) {
                float ex = __expf(s_alpha[j] - m);
                s_alpha[j] = ex;
                sum += ex;
            }
#pragma unroll
            for (int o = 16; o; o >>= 1) sum += __shfl_xor_sync(0xffffffffu, sum, o);
            float rinv = 1.f / fmaxf(sum, 1e-9f);
            for (int j = tid; j < deg; j += 32) s_alpha[j] *= rinv;
        }
        __syncthreads();
        float acc = 0.f;
#pragma unroll 4
        for (int j = 0; j < deg; j++)
            acc = fmaf(s_alpha[j], g_feat1[(size_t)s_src[j] * OUT_DIM + tid], acc);
        out[(size_t)n * OUT_DIM + tid] = acc;
    } else {
        if (tid < 32) {
            float m = NEG_INF;
            for (int j = tid; j < deg; j += 32)
                m = fmaxf(m, lrelu(g_el1[g_csrsrc[beg + j]] + ern));
#pragma unroll
            for (int o = 16; o; o >>= 1) m = fmaxf(m, __shfl_xor_sync(0xffffffffu, m, o));
            float sum = 0.f;
            for (int j = tid; j < deg; j += 32)
                sum += __expf(lrelu(g_el1[g_csrsrc[beg + j]] + ern) - m);
#pragma unroll
            for (int o = 16; o; o >>= 1) sum += __shfl_xor_sync(0xffffffffu, sum, o);
            if (tid == 0) { s_mr[0] = m; s_mr[1] = 1.f / fmaxf(sum, 1e-9f); }
        }
        __syncthreads();
        const float m = s_mr[0], rinv = s_mr[1];
        float acc = 0.f;
        for (int j = 0; j < deg; j++) {
            int s = g_csrsrc[beg + j];
            float a = __expf(lrelu(g_el1[s] + ern) - m) * rinv;
            acc = fmaf(a, g_feat1[(size_t)s * OUT_DIM + tid], acc);
        }
        out[(size_t)n * OUT_DIM + tid] = acc;
    }
}

// ---------------- launch ----------------
extern "C" void kernel_launch(void* const* d_in, const int* in_sizes, int n_in,
                              void* d_out, int out_size)
{
    const float* features = (const float*)d_in[0];
    const int*   src      = (const int*)d_in[1];
    const int*   dst      = (const int*)d_in[2];
    const float* W0       = (const float*)d_in[3];
    const float* al0      = (const float*)d_in[4];
    const float* ar0      = (const float*)d_in[5];
    const float* W1       = (const float*)d_in[6];
    const float* al1      = (const float*)d_in[7];
    const float* ar1      = (const float*)d_in[8];
    float* out = (float*)d_out;

    float *feat0p = nullptr, *h1p = nullptr, *feat1p = nullptr;
    cudaGetSymbolAddress((void**)&feat0p, g_feat0);
    cudaGetSymbolAddress((void**)&h1p,    g_h1);
    cudaGetSymbolAddress((void**)&feat1p, g_feat1);

    // CSR by dst
    zero_counts_kernel<<<(N_NODES + 255) / 256, 256>>>();
    count_kernel<<<(N_EDGES + 255) / 256, 256>>>(dst);
    scan_kernel<<<1, 1024>>>();
    scatter_kernel<<<(N_EDGES + 255) / 256, 256>>>(src, dst);

    // layer 0
    sgemm_kernel<<<dim3(D0 / GBN, (N_NODES + GBM - 1) / GBM), 256>>>(
        features, W0, feat0p, N_NODES, D0, IN_FEATS);
    eler0_kernel<<<N_NODES, 256>>>(al0, ar0);
    gat_agg0_kernel<<<N_NODES, 256>>>();

    // layer 1
    sgemm_kernel<<<dim3(OUT_DIM / GBN, (N_NODES + GBM - 1) / GBM), 256>>>(
        h1p, W1, feat1p, N_NODES, OUT_DIM, D0);
    eler1_kernel<<<(N_NODES + 7) / 8, 256>>>(al1, ar1);
    gat_agg1_kernel<<<N_NODES, 64>>>(out);
}

// round 4
// speedup vs baseline: 1.0004x; 1.0004x over previous
#include <cuda_runtime.h>
#include <cuda_bf16.h>
#include <cstdint>

#define N_NODES 20000
#define N_EDGES 320000
#define IN_FEATS 512
#define HIDDEN 64
#define HEADS 8
#define D0 512           // HEADS*HIDDEN
#define OUT_DIM 64
#define NEG_SLOPE 0.2f
#define MAXDEG 512

// ---------------- scratch (device globals; no allocation allowed) ----------------
__device__ float g_feat0[(size_t)N_NODES * D0];     // layer0 projected feats [N, 8*64]
__device__ float g_h1[(size_t)N_NODES * D0];        // elu(aggregated layer0)  [N, 512]
__device__ float g_feat1[(size_t)N_NODES * OUT_DIM];// layer1 projected feats [N, 64]
__device__ float g_el0[N_NODES * HEADS];
__device__ float g_er0[N_NODES * HEADS];
__device__ float g_el1[N_NODES];
__device__ float g_er1[N_NODES];
__device__ int   g_counts[N_NODES];
__device__ int   g_rowoff[N_NODES + 1];
__device__ int   g_cursor[N_NODES];
__device__ int   g_csrsrc[N_EDGES];

__device__ __forceinline__ float lrelu(float x) { return x > 0.f ? x : NEG_SLOPE * x; }
#define NEG_INF __int_as_float(0xff800000)

// ---------------- CSR build ----------------
__global__ void zero_counts_kernel() {
    int i = blockIdx.x * blockDim.x + threadIdx.x;
    if (i < N_NODES) g_counts[i] = 0;
}

__global__ void count_kernel(const int* __restrict__ dst) {
    int e = blockIdx.x * blockDim.x + threadIdx.x;
    if (e < N_EDGES) atomicAdd(&g_counts[dst[e]], 1);
}

__global__ void scan_kernel() {
    __shared__ int s[1024];
    const int tid = threadIdx.x;
    const int CH = (N_NODES + 1023) / 1024;   // 20
    int b = tid * CH;
    int e = min(b + CH, N_NODES);
    int local = 0;
    for (int i = b; i < e; i++) local += g_counts[i];
    s[tid] = local;
    __syncthreads();
    for (int off = 1; off < 1024; off <<= 1) {
        int add = (tid >= off) ? s[tid - off] : 0;
        __syncthreads();
        s[tid] += add;
        __syncthreads();
    }
    int run = s[tid] - local;                 // exclusive prefix
    for (int i = b; i < e; i++) {
        g_rowoff[i] = run;
        g_cursor[i] = run;
        run += g_counts[i];
    }
    if (tid == 1023) g_rowoff[N_NODES] = s[1023];
}

__global__ void scatter_kernel(const int* __restrict__ src, const int* __restrict__ dst) {
    int e = blockIdx.x * blockDim.x + threadIdx.x;
    if (e < N_EDGES) {
        int pos = atomicAdd(&g_cursor[dst[e]], 1);
        g_csrsrc[pos] = src[e];
    }
}

// ---------------- fp32 SGEMM: C[M,N] = A[M,K] * B[K,N] ----------------
// BM=128, BN=64, BK=16, 256 threads, 8x4 per thread.
#define GBM 128
#define GBN 64
#define GBK 16
__global__ void __launch_bounds__(256) sgemm_kernel(
    const float* __restrict__ A, const float* __restrict__ B, float* __restrict__ C,
    int M, int N, int K)
{
    __shared__ float As[GBK][GBM];
    __shared__ float Bs[GBK][GBN];
    const int bm = blockIdx.y * GBM;
    const int bn = blockIdx.x * GBN;
    const int tid = threadIdx.x;
    const int tx = tid & 15, ty = tid >> 4;
    float acc[8][4];
#pragma unroll
    for (int i = 0; i < 8; i++)
#pragma unroll
        for (int j = 0; j < 4; j++) acc[i][j] = 0.f;

    const int arow = tid >> 2;          // 0..63
    const int acol = (tid & 3) << 2;    // 0,4,8,12
    const int brow = tid >> 4;          // 0..15
    const int bcol = (tid & 15) << 2;   // 0..60

    for (int k0 = 0; k0 < K; k0 += GBK) {
#pragma unroll
        for (int r = 0; r < 2; r++) {
            int m = arow + (r << 6);
            float4 v = make_float4(0.f, 0.f, 0.f, 0.f);
            if (bm + m < M) v = *(const float4*)(A + (size_t)(bm + m) * K + (k0 + acol));
            As[acol + 0][m] = v.x;
            As[acol + 1][m] = v.y;
            As[acol + 2][m] = v.z;
            As[acol + 3][m] = v.w;
        }
        *(float4*)&Bs[brow][bcol] = *(const float4*)(B + (size_t)(k0 + brow) * N + (bn + bcol));
        __syncthreads();
#pragma unroll
        for (int k = 0; k < GBK; k++) {
            float a[8], b[4];
#pragma unroll
            for (int i = 0; i < 8; i++) a[i] = As[k][ty * 8 + i];
#pragma unroll
            for (int j = 0; j < 4; j++) b[j] = Bs[k][tx * 4 + j];
#pragma unroll
            for (int i = 0; i < 8; i++)
#pragma unroll
                for (int j = 0; j < 4; j++)
                    acc[i][j] = fmaf(a[i], b[j], acc[i][j]);
        }
        __syncthreads();
    }
#pragma unroll
    for (int i = 0; i < 8; i++) {
        int m = bm + ty * 8 + i;
        if (m < M)
            *(float4*)(C + (size_t)m * N + bn + tx * 4) =
                make_float4(acc[i][0], acc[i][1], acc[i][2], acc[i][3]);
    }
}

// ---------------- el/er for layer 0: warp per (node, head) ----------------
__global__ void __launch_bounds__(256) eler0_kernel(const float* __restrict__ al,
                                                    const float* __restrict__ ar)
{
    const int n = blockIdx.x;               // one node per block
    const int h = threadIdx.x >> 5;         // 8 warps = 8 heads
    const int lane = threadIdx.x & 31;
    const float* f = g_feat0 + (size_t)n * D0 + h * HIDDEN;
    float2 fv = *(const float2*)(f + lane * 2);
    float2 alv = *(const float2*)(al + h * HIDDEN + lane * 2);
    float2 arv = *(const float2*)(ar + h * HIDDEN + lane * 2);
    float sl = fv.x * alv.x + fv.y * alv.y;
    float sr = fv.x * arv.x + fv.y * arv.y;
#pragma unroll
    for (int o = 16; o; o >>= 1) {
        sl += __shfl_xor_sync(0xffffffffu, sl, o);
        sr += __shfl_xor_sync(0xffffffffu, sr, o);
    }
    if (lane == 0) {
        g_el0[n * HEADS + h] = sl;
        g_er0[n * HEADS + h] = sr;
    }
}

// ---------------- el/er for layer 1: warp per node ----------------
__global__ void __launch_bounds__(256) eler1_kernel(const float* __restrict__ al,
                                                    const float* __restrict__ ar)
{
    const int gw = blockIdx.x * 8 + (threadIdx.x >> 5);
    const int lane = threadIdx.x & 31;
    if (gw >= N_NODES) return;
    const float* f = g_feat1 + (size_t)gw * OUT_DIM;
    float2 fv = *(const float2*)(f + lane * 2);
    float2 alv = *(const float2*)(al + lane * 2);
    float2 arv = *(const float2*)(ar + lane * 2);
    float sl = fv.x * alv.x + fv.y * alv.y;
    float sr = fv.x * arv.x + fv.y * arv.y;
#pragma unroll
    for (int o = 16; o; o >>= 1) {
        sl += __shfl_xor_sync(0xffffffffu, sl, o);
        sr += __shfl_xor_sync(0xffffffffu, sr, o);
    }
    if (lane == 0) {
        g_el1[gw] = sl;
        g_er1[gw] = sr;
    }
}

// ---------------- layer-0 softmax + aggregation + ELU: block per dst node ----------------
__global__ void __launch_bounds__(256) gat_agg0_kernel()
{
    const int n = blockIdx.x;
    const int beg = g_rowoff[n];
    const int deg = g_rowoff[n + 1] - beg;
    const int tid = threadIdx.x;

    if (deg == 0) {   // elu(0) = 0
        g_h1[(size_t)n * D0 + tid] = 0.f;
        g_h1[(size_t)n * D0 + tid + 256] = 0.f;
        return;
    }

    __shared__ float s_alpha[HEADS][MAXDEG];
    __shared__ int   s_src[MAXDEG];
    __shared__ float s_m[HEADS], s_rinv[HEADS];

    const int h = tid >> 5;
    const int lane = tid & 31;
    const float ern = g_er0[n * HEADS + h];

    const int c0 = tid, c1 = tid + 256;
    const int h0 = c0 >> 6, h1i = c1 >> 6;

    if (deg <= MAXDEG) {
        for (int j = tid; j < deg; j += 256) s_src[j] = g_csrsrc[beg + j];
        __syncthreads();

        float m = NEG_INF;
        for (int j = lane; j < deg; j += 32) {
            float e = lrelu(g_el0[s_src[j] * HEADS + h] + ern);
            s_alpha[h][j] = e;
            m = fmaxf(m, e);
        }
#pragma unroll
        for (int o = 16; o; o >>= 1) m = fmaxf(m, __shfl_xor_sync(0xffffffffu, m, o));
        float sum = 0.f;
        for (int j = lane; j < deg; j += 32) {
            float ex = __expf(s_alpha[h][j] - m);
            s_alpha[h][j] = ex;
            sum += ex;
        }
#pragma unroll
        for (int o = 16; o; o >>= 1) sum += __shfl_xor_sync(0xffffffffu, sum, o);
        float rinv = 1.f / fmaxf(sum, 1e-9f);
        for (int j = lane; j < deg; j += 32) s_alpha[h][j] *= rinv;
        __syncthreads();

        float acc0 = 0.f, acc1 = 0.f;
#pragma unroll 4
        for (int j = 0; j < deg; j++) {
            const float* fr = g_feat0 + (size_t)s_src[j] * D0;
            acc0 = fmaf(s_alpha[h0][j], fr[c0], acc0);
            acc1 = fmaf(s_alpha[h1i][j], fr[c1], acc1);
        }
        g_h1[(size_t)n * D0 + c0] = acc0 > 0.f ? acc0 : __expf(acc0) - 1.f;
        g_h1[(size_t)n * D0 + c1] = acc1 > 0.f ? acc1 : __expf(acc1) - 1.f;
    } else {
        // huge-degree fallback: recompute e, no SMEM caches
        float m = NEG_INF;
        for (int j = lane; j < deg; j += 32)
            m = fmaxf(m, lrelu(g_el0[g_csrsrc[beg + j] * HEADS + h] + ern));
#pragma unroll
        for (int o = 16; o; o >>= 1) m = fmaxf(m, __shfl_xor_sync(0xffffffffu, m, o));
        float sum = 0.f;
        for (int j = lane; j < deg; j += 32)
            sum += __expf(lrelu(g_el0[g_csrsrc[beg + j] * HEADS + h] + ern) - m);
#pragma unroll
        for (int o = 16; o; o >>= 1) sum += __shfl_xor_sync(0xffffffffu, sum, o);
        if (lane == 0) { s_m[h] = m; s_rinv[h] = 1.f / fmaxf(sum, 1e-9f); }
        __syncthreads();

        const float m0 = s_m[h0], r0 = s_rinv[h0];
        const float m1 = s_m[h1i], r1 = s_rinv[h1i];
        const float e0n = g_er0[n * HEADS + h0], e1n = g_er0[n * HEADS + h1i];
        float acc0 = 0.f, acc1 = 0.f;
        for (int j = 0; j < deg; j++) {
            int s = g_csrsrc[beg + j];
            float a0 = __expf(lrelu(g_el0[s * HEADS + h0] + e0n) - m0) * r0;
            float a1 = __expf(lrelu(g_el0[s * HEADS + h1i] + e1n) - m1) * r1;
            const float* fr = g_feat0 + (size_t)s * D0;
            acc0 = fmaf(a0, fr[c0], acc0);
            acc1 = fmaf(a1, fr[c1], acc1);
        }
        g_h1[(size_t)n * D0 + c0] = acc0 > 0.f ? acc0 : __expf(acc0) - 1.f;
        g_h1[(size_t)n * D0 + c1] = acc1 > 0.f ? acc1 : __expf(acc1) - 1.f;
    }
}

// ---------------- layer-1 softmax + aggregation (1 head, 64 dims): block per dst node ----------------
__global__ void __launch_bounds__(64) gat_agg1_kernel(float* __restrict__ out)
{
    const int n = blockIdx.x;
    const int beg = g_rowoff[n];
    const int deg = g_rowoff[n + 1] - beg;
    const int tid = threadIdx.x;

    if (deg == 0) { out[(size_t)n * OUT_DIM + tid] = 0.f; return; }

    __shared__ float s_alpha[MAXDEG];
    __shared__ int   s_src[MAXDEG];
    __shared__ float s_mr[2];

    const float ern = g_er1[n];

    if (deg <= MAXDEG) {
        for (int j = tid; j < deg; j += 64) s_src[j] = g_csrsrc[beg + j];
        __syncthreads();
        if (tid < 32) {
            float m = NEG_INF;
            for (int j = tid; j < deg; j += 32) {
                float e = lrelu(g_el1[s_src[j]] + ern);
                s_alpha[j] = e;
                m = fmaxf(m, e);
            }
#pragma unroll
            for (int o = 16; o; o >>= 1) m = fmaxf(m, __shfl_xor_sync(0xffffffffu, m, o));
            float sum = 0.f;
            for (int j = tid; j < deg; j += 32) {
                float ex = __expf(s_alpha[j] - m);
                s_alpha[j] = ex;
                sum += ex;
            }
#pragma unroll
            for (int o = 16; o; o >>= 1) sum += __shfl_xor_sync(0xffffffffu, sum, o);
            float rinv = 1.f / fmaxf(sum, 1e-9f);
            for (int j = tid; j < deg; j += 32) s_alpha[j] *= rinv;
        }
        __syncthreads();
        float acc = 0.f;
#pragma unroll 4
        for (int j = 0; j < deg; j++)
            acc = fmaf(s_alpha[j], g_feat1[(size_t)s_src[j] * OUT_DIM + tid], acc);
        out[(size_t)n * OUT_DIM + tid] = acc;
    } else {
        if (tid < 32) {
            float m = NEG_INF;
            for (int j = tid; j < deg; j += 32)
                m = fmaxf(m, lrelu(g_el1[g_csrsrc[beg + j]] + ern));
#pragma unroll
            for (int o = 16; o; o >>= 1) m = fmaxf(m, __shfl_xor_sync(0xffffffffu, m, o));
            float sum = 0.f;
            for (int j = tid; j < deg; j += 32)
                sum += __expf(lrelu(g_el1[g_csrsrc[beg + j]] + ern) - m);
#pragma unroll
            for (int o = 16; o; o >>= 1) sum += __shfl_xor_sync(0xffffffffu, sum, o);
            if (tid == 0) { s_mr[0] = m; s_mr[1] = 1.f / fmaxf(sum, 1e-9f); }
        }
        __syncthreads();
        const float m = s_mr[0], rinv = s_mr[1];
        float acc = 0.f;
        for (int j = 0; j < deg; j++) {
            int s = g_csrsrc[beg + j];
            float a = __expf(lrelu(g_el1[s] + ern) - m) * rinv;
            acc = fmaf(a, g_feat1[(size_t)s * OUT_DIM + tid], acc);
        }
        out[(size_t)n * OUT_DIM + tid] = acc;
    }
}

// ---------------- launch ----------------
extern "C" void kernel_launch(void* const* d_in, const int* in_sizes, int n_in,
                              void* d_out, int out_size)
{
    const float* features = (const float*)d_in[0];
    const int*   src      = (const int*)d_in[1];
    const int*   dst      = (const int*)d_in[2];
    const float* W0       = (const float*)d_in[3];
    const float* al0      = (const float*)d_in[4];
    const float* ar0      = (const float*)d_in[5];
    const float* W1       = (const float*)d_in[6];
    const float* al1      = (const float*)d_in[7];
    const float* ar1      = (const float*)d_in[8];
    float* out = (float*)d_out;

    float *feat0p = nullptr, *h1p = nullptr, *feat1p = nullptr;
    cudaGetSymbolAddress((void**)&feat0p, g_feat0);
    cudaGetSymbolAddress((void**)&h1p,    g_h1);
    cudaGetSymbolAddress((void**)&feat1p, g_feat1);

    // CSR by dst
    zero_counts_kernel<<<(N_NODES + 255) / 256, 256>>>();
    count_kernel<<<(N_EDGES + 255) / 256, 256>>>(dst);
    scan_kernel<<<1, 1024>>>();
    scatter_kernel<<<(N_EDGES + 255) / 256, 256>>>(src, dst);

    // layer 0
    sgemm_kernel<<<dim3(D0 / GBN, (N_NODES + GBM - 1) / GBM), 256>>>(
        features, W0, feat0p, N_NODES, D0, IN_FEATS);
    eler0_kernel<<<N_NODES, 256>>>(al0, ar0);
    gat_agg0_kernel<<<N_NODES, 256>>>();

    // layer 1
    sgemm_kernel<<<dim3(OUT_DIM / GBN, (N_NODES + GBM - 1) / GBM), 256>>>(
        h1p, W1, feat1p, N_NODES, OUT_DIM, D0);
    eler1_kernel<<<(N_NODES + 7) / 8, 256>>>(al1, ar1);
    gat_agg1_kernel<<<N_NODES, 64>>>(out);
}

// round 5
// speedup vs baseline: 1.2194x; 1.2190x over previous
#include <cuda_runtime.h>
#include <cuda_bf16.h>
#include <cstdint>

#define N_NODES 20000
#define N_EDGES 320000
#define IN_FEATS 512
#define HIDDEN 64
#define HEADS 8
#define D0 512           // HEADS*HIDDEN
#define OUT_DIM 64
#define NEG_SLOPE 0.2f
#define MAXDEG 512

// ---------------- scratch (device globals; no allocation allowed) ----------------
__device__ float g_feat0[(size_t)N_NODES * D0];     // layer0 projected feats [N, 8*64]
__device__ float g_h1[(size_t)N_NODES * D0];        // elu(aggregated layer0)  [N, 512]
__device__ float g_feat1[(size_t)N_NODES * OUT_DIM];// layer1 projected feats [N, 64]
__device__ float g_el0[N_NODES * HEADS];
__device__ float g_er0[N_NODES * HEADS];
__device__ float g_el1[N_NODES];
__device__ float g_er1[N_NODES];
__device__ int   g_counts[N_NODES];
__device__ int   g_rowoff[N_NODES + 1];
__device__ int   g_cursor[N_NODES];
__device__ int   g_csrsrc[N_EDGES];

__device__ __forceinline__ float lrelu(float x) { return x > 0.f ? x : NEG_SLOPE * x; }
#define NEG_INF __int_as_float(0xff800000)

// ---------------- CSR build ----------------
__global__ void zero_counts_kernel() {
    int i = blockIdx.x * blockDim.x + threadIdx.x;
    if (i < N_NODES) g_counts[i] = 0;
}

__global__ void count_kernel(const int* __restrict__ dst) {
    int e = blockIdx.x * blockDim.x + threadIdx.x;
    if (e < N_EDGES) atomicAdd(&g_counts[dst[e]], 1);
}

__global__ void scan_kernel() {
    __shared__ int s[1024];
    const int tid = threadIdx.x;
    const int CH = (N_NODES + 1023) / 1024;   // 20
    int b = tid * CH;
    int e = min(b + CH, N_NODES);
    int local = 0;
    for (int i = b; i < e; i++) local += g_counts[i];
    s[tid] = local;
    __syncthreads();
    for (int off = 1; off < 1024; off <<= 1) {
        int add = (tid >= off) ? s[tid - off] : 0;
        __syncthreads();
        s[tid] += add;
        __syncthreads();
    }
    int run = s[tid] - local;                 // exclusive prefix
    for (int i = b; i < e; i++) {
        g_rowoff[i] = run;
        g_cursor[i] = run;
        run += g_counts[i];
    }
    if (tid == 1023) g_rowoff[N_NODES] = s[1023];
}

__global__ void scatter_kernel(const int* __restrict__ src, const int* __restrict__ dst) {
    int e = blockIdx.x * blockDim.x + threadIdx.x;
    if (e < N_EDGES) {
        int pos = atomicAdd(&g_cursor[dst[e]], 1);
        g_csrsrc[pos] = src[e];
    }
}

// ================= tf32 3-split tensor-core GEMM =================
// C[M,N] = A[M,K] * B[K,N], fp32 in/out, ~fp32 accuracy via
// A = Ah + Al, B = Bh + Bl (tf32 splits); C ≈ Ah*Bh + Ah*Bl + Al*Bh.
// Tiles: BM=128, BN=64, BK=16. 256 threads = 8 warps, warp tile 32x32.
// mma.sync.aligned.m16n8k8.row.col.f32.tf32.tf32.f32
#define TBM 128
#define TBN 64
#define TBK 16
#define A_STRIDE 20   // TBK + 4 pad -> conflict-free frag loads
#define B_STRIDE 72   // TBN + 8 pad -> conflict-free frag loads

__device__ __forceinline__ void tf32split(float v, uint32_t& h, uint32_t& l) {
    uint32_t uh;
    asm("cvt.rna.tf32.f32 %0, %1;" : "=r"(uh) : "f"(v));
    float fl = v - __uint_as_float(uh);
    uint32_t ul;
    asm("cvt.rna.tf32.f32 %0, %1;" : "=r"(ul) : "f"(fl));
    h = uh; l = ul;
}

__device__ __forceinline__ void cpasync16(void* smem, const void* g, bool valid) {
    uint32_t sa = (uint32_t)__cvta_generic_to_shared(smem);
    int sz = valid ? 16 : 0;
    asm volatile("cp.async.cg.shared.global [%0], [%1], 16, %2;" :: "r"(sa), "l"(g), "r"(sz));
}

__device__ __forceinline__ void mma8(float* c, const uint32_t* a, const uint32_t* b) {
    asm volatile(
        "mma.sync.aligned.m16n8k8.row.col.f32.tf32.tf32.f32 "
        "{%0,%1,%2,%3}, {%4,%5,%6,%7}, {%8,%9}, {%0,%1,%2,%3};"
        : "+f"(c[0]), "+f"(c[1]), "+f"(c[2]), "+f"(c[3])
        : "r"(a[0]), "r"(a[1]), "r"(a[2]), "r"(a[3]), "r"(b[0]), "r"(b[1]));
}

__global__ void __launch_bounds__(256, 2) tf32_gemm_kernel(
    const float* __restrict__ A, const float* __restrict__ B, float* __restrict__ C,
    int M, int N, int K)
{
    __shared__ float As[2][TBM][A_STRIDE];
    __shared__ float Bs[2][TBK][B_STRIDE];

    const int bm = blockIdx.y * TBM;
    const int bn = blockIdx.x * TBN;
    const int tid = threadIdx.x;
    const int lane = tid & 31;
    const int warp = tid >> 5;
    const int wm = warp >> 1;       // 0..3
    const int wn = warp & 1;        // 0..1
    const int quad = lane >> 2;     // 0..7
    const int kq = lane & 3;        // 0..3

    // global load assignments
    const int a_m  = tid >> 2;            // 0..63  (two passes: +64)
    const int a_kc = (tid & 3) << 2;      // 0,4,8,12
    const int b_k  = tid >> 4;            // 0..15
    const int b_nc = (tid & 15) << 2;     // 0..60

    float acc[2][4][4];
#pragma unroll
    for (int mi = 0; mi < 2; mi++)
#pragma unroll
        for (int ni = 0; ni < 4; ni++)
#pragma unroll
            for (int r = 0; r < 4; r++) acc[mi][ni][r] = 0.f;

    const int T = K / TBK;   // K divisible by 16 for all our shapes

    // ---- prologue: stage tile 0 into buffer 0 ----
    {
        const int kt = 0;
#pragma unroll
        for (int p = 0; p < 2; p++) {
            int m = a_m + (p << 6);
            cpasync16(&As[0][m][a_kc], A + (size_t)(bm + m) * K + kt + a_kc, (bm + m) < M);
        }
        cpasync16(&Bs[0][b_k][b_nc], B + (size_t)(kt + b_k) * N + bn + b_nc, true);
        asm volatile("cp.async.commit_group;");
    }

    for (int t = 0; t < T; t++) {
        const int cur = t & 1;
        if (t + 1 < T) {
            const int nxt = cur ^ 1;
            const int kt = (t + 1) * TBK;
#pragma unroll
            for (int p = 0; p < 2; p++) {
                int m = a_m + (p << 6);
                cpasync16(&As[nxt][m][a_kc], A + (size_t)(bm + m) * K + kt + a_kc, (bm + m) < M);
            }
            cpasync16(&Bs[nxt][b_k][b_nc], B + (size_t)(kt + b_k) * N + bn + b_nc, true);
            asm volatile("cp.async.commit_group;");
            asm volatile("cp.async.wait_group 1;");
        } else {
            asm volatile("cp.async.wait_group 0;");
        }
        __syncthreads();

        // ---- compute on buffer cur: 2 k-steps of 8 ----
#pragma unroll
        for (int ks = 0; ks < 2; ks++) {
            const int kb = ks * 8 + kq;
            uint32_t Ah[2][4], Al[2][4];
#pragma unroll
            for (int mi = 0; mi < 2; mi++) {
#pragma unroll
                for (int r = 0; r < 4; r++) {
                    int row = wm * 32 + mi * 16 + quad + ((r & 1) << 3);
                    int col = kb + ((r >> 1) << 2);
                    tf32split(As[cur][row][col], Ah[mi][r], Al[mi][r]);
                }
            }
            uint32_t Bh[4][2], Bl[4][2];
#pragma unroll
            for (int ni = 0; ni < 4; ni++) {
#pragma unroll
                for (int r = 0; r < 2; r++) {
                    int krow = kb + (r << 2);
                    int ncol = wn * 32 + ni * 8 + quad;
                    tf32split(Bs[cur][krow][ncol], Bh[ni][r], Bl[ni][r]);
                }
            }
#pragma unroll
            for (int mi = 0; mi < 2; mi++) {
#pragma unroll
                for (int ni = 0; ni < 4; ni++) {
                    mma8(acc[mi][ni], Ah[mi], Bh[ni]);   // hi*hi
                    mma8(acc[mi][ni], Ah[mi], Bl[ni]);   // hi*lo
                    mma8(acc[mi][ni], Al[mi], Bh[ni]);   // lo*hi
                }
            }
        }
        __syncthreads();
    }

    // ---- epilogue ----
#pragma unroll
    for (int mi = 0; mi < 2; mi++) {
#pragma unroll
        for (int ni = 0; ni < 4; ni++) {
            int row0 = bm + wm * 32 + mi * 16 + quad;
            int col = bn + wn * 32 + ni * 8 + kq * 2;
            if (row0 < M)
                *(float2*)(C + (size_t)row0 * N + col) =
                    make_float2(acc[mi][ni][0], acc[mi][ni][1]);
            int row1 = row0 + 8;
            if (row1 < M)
                *(float2*)(C + (size_t)row1 * N + col) =
                    make_float2(acc[mi][ni][2], acc[mi][ni][3]);
        }
    }
}

// ---------------- el/er for layer 0: warp per (node, head) ----------------
__global__ void __launch_bounds__(256) eler0_kernel(const float* __restrict__ al,
                                                    const float* __restrict__ ar)
{
    const int n = blockIdx.x;               // one node per block
    const int h = threadIdx.x >> 5;         // 8 warps = 8 heads
    const int lane = threadIdx.x & 31;
    const float* f = g_feat0 + (size_t)n * D0 + h * HIDDEN;
    float2 fv = *(const float2*)(f + lane * 2);
    float2 alv = *(const float2*)(al + h * HIDDEN + lane * 2);
    float2 arv = *(const float2*)(ar + h * HIDDEN + lane * 2);
    float sl = fv.x * alv.x + fv.y * alv.y;
    float sr = fv.x * arv.x + fv.y * arv.y;
#pragma unroll
    for (int o = 16; o; o >>= 1) {
        sl += __shfl_xor_sync(0xffffffffu, sl, o);
        sr += __shfl_xor_sync(0xffffffffu, sr, o);
    }
    if (lane == 0) {
        g_el0[n * HEADS + h] = sl;
        g_er0[n * HEADS + h] = sr;
    }
}

// ---------------- el/er for layer 1: warp per node ----------------
__global__ void __launch_bounds__(256) eler1_kernel(const float* __restrict__ al,
                                                    const float* __restrict__ ar)
{
    const int gw = blockIdx.x * 8 + (threadIdx.x >> 5);
    const int lane = threadIdx.x & 31;
    if (gw >= N_NODES) return;
    const float* f = g_feat1 + (size_t)gw * OUT_DIM;
    float2 fv = *(const float2*)(f + lane * 2);
    float2 alv = *(const float2*)(al + lane * 2);
    float2 arv = *(const float2*)(ar + lane * 2);
    float sl = fv.x * alv.x + fv.y * alv.y;
    float sr = fv.x * arv.x + fv.y * arv.y;
#pragma unroll
    for (int o = 16; o; o >>= 1) {
        sl += __shfl_xor_sync(0xffffffffu, sl, o);
        sr += __shfl_xor_sync(0xffffffffu, sr, o);
    }
    if (lane == 0) {
        g_el1[gw] = sl;
        g_er1[gw] = sr;
    }
}

// ---------------- layer-0 softmax + aggregation + ELU: block per dst node ----------------
__global__ void __launch_bounds__(256) gat_agg0_kernel()
{
    const int n = blockIdx.x;
    const int beg = g_rowoff[n];
    const int deg = g_rowoff[n + 1] - beg;
    const int tid = threadIdx.x;

    if (deg == 0) {   // elu(0) = 0
        g_h1[(size_t)n * D0 + tid] = 0.f;
        g_h1[(size_t)n * D0 + tid + 256] = 0.f;
        return;
    }

    __shared__ float s_alpha[HEADS][MAXDEG];
    __shared__ int   s_src[MAXDEG];
    __shared__ float s_m[HEADS], s_rinv[HEADS];

    const int h = tid >> 5;
    const int lane = tid & 31;
    const float ern = g_er0[n * HEADS + h];

    const int c0 = tid, c1 = tid + 256;
    const int h0 = c0 >> 6, h1i = c1 >> 6;

    if (deg <= MAXDEG) {
        for (int j = tid; j < deg; j += 256) s_src[j] = g_csrsrc[beg + j];
        __syncthreads();

        float m = NEG_INF;
        for (int j = lane; j < deg; j += 32) {
            float e = lrelu(g_el0[s_src[j] * HEADS + h] + ern);
            s_alpha[h][j] = e;
            m = fmaxf(m, e);
        }
#pragma unroll
        for (int o = 16; o; o >>= 1) m = fmaxf(m, __shfl_xor_sync(0xffffffffu, m, o));
        float sum = 0.f;
        for (int j = lane; j < deg; j += 32) {
            float ex = __expf(s_alpha[h][j] - m);
            s_alpha[h][j] = ex;
            sum += ex;
        }
#pragma unroll
        for (int o = 16; o; o >>= 1) sum += __shfl_xor_sync(0xffffffffu, sum, o);
        float rinv = 1.f / fmaxf(sum, 1e-9f);
        for (int j = lane; j < deg; j += 32) s_alpha[h][j] *= rinv;
        __syncthreads();

        float acc0 = 0.f, acc1 = 0.f;
#pragma unroll 4
        for (int j = 0; j < deg; j++) {
            const float* fr = g_feat0 + (size_t)s_src[j] * D0;
            acc0 = fmaf(s_alpha[h0][j], fr[c0], acc0);
            acc1 = fmaf(s_alpha[h1i][j], fr[c1], acc1);
        }
        g_h1[(size_t)n * D0 + c0] = acc0 > 0.f ? acc0 : __expf(acc0) - 1.f;
        g_h1[(size_t)n * D0 + c1] = acc1 > 0.f ? acc1 : __expf(acc1) - 1.f;
    } else {
        // huge-degree fallback: recompute e, no SMEM caches
        float m = NEG_INF;
        for (int j = lane; j < deg; j += 32)
            m = fmaxf(m, lrelu(g_el0[g_csrsrc[beg + j] * HEADS + h] + ern));
#pragma unroll
        for (int o = 16; o; o >>= 1) m = fmaxf(m, __shfl_xor_sync(0xffffffffu, m, o));
        float sum = 0.f;
        for (int j = lane; j < deg; j += 32)
            sum += __expf(lrelu(g_el0[g_csrsrc[beg + j] * HEADS + h] + ern) - m);
#pragma unroll
        for (int o = 16; o; o >>= 1) sum += __shfl_xor_sync(0xffffffffu, sum, o);
        if (lane == 0) { s_m[h] = m; s_rinv[h] = 1.f / fmaxf(sum, 1e-9f); }
        __syncthreads();

        const float m0 = s_m[h0], r0 = s_rinv[h0];
        const float m1 = s_m[h1i], r1 = s_rinv[h1i];
        const float e0n = g_er0[n * HEADS + h0], e1n = g_er0[n * HEADS + h1i];
        float acc0 = 0.f, acc1 = 0.f;
        for (int j = 0; j < deg; j++) {
            int s = g_csrsrc[beg + j];
            float a0 = __expf(lrelu(g_el0[s * HEADS + h0] + e0n) - m0) * r0;
            float a1 = __expf(lrelu(g_el0[s * HEADS + h1i] + e1n) - m1) * r1;
            const float* fr = g_feat0 + (size_t)s * D0;
            acc0 = fmaf(a0, fr[c0], acc0);
            acc1 = fmaf(a1, fr[c1], acc1);
        }
        g_h1[(size_t)n * D0 + c0] = acc0 > 0.f ? acc0 : __expf(acc0) - 1.f;
        g_h1[(size_t)n * D0 + c1] = acc1 > 0.f ? acc1 : __expf(acc1) - 1.f;
    }
}

// ---------------- layer-1 softmax + aggregation (1 head, 64 dims): block per dst node ----------------
__global__ void __launch_bounds__(64) gat_agg1_kernel(float* __restrict__ out)
{
    const int n = blockIdx.x;
    const int beg = g_rowoff[n];
    const int deg = g_rowoff[n + 1] - beg;
    const int tid = threadIdx.x;

    if (deg == 0) { out[(size_t)n * OUT_DIM + tid] = 0.f; return; }

    __shared__ float s_alpha[MAXDEG];
    __shared__ int   s_src[MAXDEG];
    __shared__ float s_mr[2];

    const float ern = g_er1[n];

    if (deg <= MAXDEG) {
        for (int j = tid; j < deg; j += 64) s_src[j] = g_csrsrc[beg + j];
        __syncthreads();
        if (tid < 32) {
            float m = NEG_INF;
            for (int j = tid; j < deg; j += 32) {
                float e = lrelu(g_el1[s_src[j]] + ern);
                s_alpha[j] = e;
                m = fmaxf(m, e);
            }
#pragma unroll
            for (int o = 16; o; o >>= 1) m = fmaxf(m, __shfl_xor_sync(0xffffffffu, m, o));
            float sum = 0.f;
            for (int j = tid; j < deg; j += 32) {
                float ex = __expf(s_alpha[j] - m);
                s_alpha[j] = ex;
                sum += ex;
            }
#pragma unroll
            for (int o = 16; o; o >>= 1) sum += __shfl_xor_sync(0xffffffffu, sum, o);
            float rinv = 1.f / fmaxf(sum, 1e-9f);
            for (int j = tid; j < deg; j += 32) s_alpha[j] *= rinv;
        }
        __syncthreads();
        float acc = 0.f;
#pragma unroll 4
        for (int j = 0; j < deg; j++)
            acc = fmaf(s_alpha[j], g_feat1[(size_t)s_src[j] * OUT_DIM + tid], acc);
        out[(size_t)n * OUT_DIM + tid] = acc;
    } else {
        if (tid < 32) {
            float m = NEG_INF;
            for (int j = tid; j < deg; j += 32)
                m = fmaxf(m, lrelu(g_el1[g_csrsrc[beg + j]] + ern));
#pragma unroll
            for (int o = 16; o; o >>= 1) m = fmaxf(m, __shfl_xor_sync(0xffffffffu, m, o));
            float sum = 0.f;
            for (int j = tid; j < deg; j += 32)
                sum += __expf(lrelu(g_el1[g_csrsrc[beg + j]] + ern) - m);
#pragma unroll
            for (int o = 16; o; o >>= 1) sum += __shfl_xor_sync(0xffffffffu, sum, o);
            if (tid == 0) { s_mr[0] = m; s_mr[1] = 1.f / fmaxf(sum, 1e-9f); }
        }
        __syncthreads();
        const float m = s_mr[0], rinv = s_mr[1];
        float acc = 0.f;
        for (int j = 0; j < deg; j++) {
            int s = g_csrsrc[beg + j];
            float a = __expf(lrelu(g_el1[s] + ern) - m) * rinv;
            acc = fmaf(a, g_feat1[(size_t)s * OUT_DIM + tid], acc);
        }
        out[(size_t)n * OUT_DIM + tid] = acc;
    }
}

// ---------------- launch ----------------
extern "C" void kernel_launch(void* const* d_in, const int* in_sizes, int n_in,
                              void* d_out, int out_size)
{
    const float* features = (const float*)d_in[0];
    const int*   src      = (const int*)d_in[1];
    const int*   dst      = (const int*)d_in[2];
    const float* W0       = (const float*)d_in[3];
    const float* al0      = (const float*)d_in[4];
    const float* ar0      = (const float*)d_in[5];
    const float* W1       = (const float*)d_in[6];
    const float* al1      = (const float*)d_in[7];
    const float* ar1      = (const float*)d_in[8];
    float* out = (float*)d_out;

    float *feat0p = nullptr, *h1p = nullptr, *feat1p = nullptr;
    cudaGetSymbolAddress((void**)&feat0p, g_feat0);
    cudaGetSymbolAddress((void**)&h1p,    g_h1);
    cudaGetSymbolAddress((void**)&feat1p, g_feat1);

    // CSR by dst
    zero_counts_kernel<<<(N_NODES + 255) / 256, 256>>>();
    count_kernel<<<(N_EDGES + 255) / 256, 256>>>(dst);
    scan_kernel<<<1, 1024>>>();
    scatter_kernel<<<(N_EDGES + 255) / 256, 256>>>(src, dst);

    const int mblocks = (N_NODES + TBM - 1) / TBM;   // 157

    // layer 0: tensor-core tf32-split GEMM
    tf32_gemm_kernel<<<dim3(D0 / TBN, mblocks), 256>>>(
        features, W0, feat0p, N_NODES, D0, IN_FEATS);
    eler0_kernel<<<N_NODES, 256>>>(al0, ar0);
    gat_agg0_kernel<<<N_NODES, 256>>>();

    // layer 1
    tf32_gemm_kernel<<<dim3(OUT_DIM / TBN, mblocks), 256>>>(
        h1p, W1, feat1p, N_NODES, OUT_DIM, D0);
    eler1_kernel<<<(N_NODES + 7) / 8, 256>>>(al1, ar1);
    gat_agg1_kernel<<<N_NODES, 64>>>(out);
}